// round 3
// baseline (speedup 1.0000x reference)
#include <cuda_runtime.h>
#include <cuda_bf16.h>

// Weighted-MSE reduction:
//   inv_freq[j] = sum(attr_num)/attr_num[j]
//   attr_w_i    = sum_j (attribute[i,j]==1) * inv_freq[j]
//   angle_w_i   = sum_j (1 - cos(ea[i,j]))
//   out         = mean_{i,d}( angle_w_i * attr_w_i * (inp-label)^2 )
//
// Kernel 1: one warp per row, float4 streaming loads, double block partials.
// Kernel 2: deterministic reduction of block partials -> scalar.

#define ROWS_PER_BLOCK 16           // 16 warps/block, 1 row/warp
#define MAX_PARTIALS   16384

__device__ double g_partials[MAX_PARTIALS];

__global__ __launch_bounds__(ROWS_PER_BLOCK * 32)
void loss_rows_kernel(const float* __restrict__ inp,
                      const float* __restrict__ label,
                      const float* __restrict__ ea,
                      const int*   __restrict__ attribute,
                      const float* __restrict__ attribute_num,
                      int B, int D)
{
    __shared__ double s_warp[ROWS_PER_BLOCK];

    const int warp = threadIdx.x >> 5;
    const int lane = threadIdx.x & 31;
    const int row  = blockIdx.x * ROWS_PER_BLOCK + warp;

    double wsum_d = 0.0;

    if (row < B) {
        // --- per-row weight, computed by lane 0 and broadcast ---
        float weight = 0.0f;
        if (lane == 0) {
            float an0 = attribute_num[0], an1 = attribute_num[1],
                  an2 = attribute_num[2], an3 = attribute_num[3],
                  an4 = attribute_num[4], an5 = attribute_num[5];
            float an_sum = an0 + an1 + an2 + an3 + an4 + an5;

            const int* at = attribute + (size_t)row * 6;
            float attr_w = 0.0f;
            attr_w += (at[0] == 1) ? an_sum / an0 : 0.0f;
            attr_w += (at[1] == 1) ? an_sum / an1 : 0.0f;
            attr_w += (at[2] == 1) ? an_sum / an2 : 0.0f;
            attr_w += (at[3] == 1) ? an_sum / an3 : 0.0f;
            attr_w += (at[4] == 1) ? an_sum / an4 : 0.0f;
            attr_w += (at[5] == 1) ? an_sum / an5 : 0.0f;

            const float* e = ea + (size_t)row * 3;
            float angle_w = (1.0f - cosf(e[0]))
                          + (1.0f - cosf(e[1]))
                          + (1.0f - cosf(e[2]));
            weight = angle_w * attr_w;
        }
        weight = __shfl_sync(0xFFFFFFFFu, weight, 0);

        // --- streaming squared-error sum over the row (float4) ---
        const float4* ip = (const float4*)(inp   + (size_t)row * D);
        const float4* lp = (const float4*)(label + (size_t)row * D);
        const int nvec = D >> 2;   // D % 4 == 0 (D = 512)

        float acc = 0.0f;
        #pragma unroll 4
        for (int v = lane; v < nvec; v += 32) {
            float4 a = ip[v];
            float4 b = lp[v];
            float d0 = a.x - b.x, d1 = a.y - b.y,
                  d2 = a.z - b.z, d3 = a.w - b.w;
            acc = fmaf(d0, d0, acc);
            acc = fmaf(d1, d1, acc);
            acc = fmaf(d2, d2, acc);
            acc = fmaf(d3, d3, acc);
        }

        // warp reduce (fp32 within the row is plenty of precision)
        #pragma unroll
        for (int off = 16; off > 0; off >>= 1)
            acc += __shfl_xor_sync(0xFFFFFFFFu, acc, off);

        wsum_d = (double)weight * (double)acc;
    }

    if (lane == 0) s_warp[warp] = wsum_d;
    __syncthreads();

    if (threadIdx.x == 0) {
        double bsum = 0.0;
        #pragma unroll
        for (int w = 0; w < ROWS_PER_BLOCK; w++) bsum += s_warp[w];
        g_partials[blockIdx.x] = bsum;
    }
}

__global__ void final_reduce_kernel(float* __restrict__ out,
                                    int n_partials, double inv_count)
{
    __shared__ double s[1024];
    double acc = 0.0;
    for (int i = threadIdx.x; i < n_partials; i += blockDim.x)
        acc += g_partials[i];
    s[threadIdx.x] = acc;
    __syncthreads();
    for (int stride = blockDim.x >> 1; stride > 0; stride >>= 1) {
        if (threadIdx.x < stride) s[threadIdx.x] += s[threadIdx.x + stride];
        __syncthreads();
    }
    if (threadIdx.x == 0)
        out[0] = (float)(s[0] * inv_count);
}

extern "C" void kernel_launch(void* const* d_in, const int* in_sizes, int n_in,
                              void* d_out, int out_size)
{
    const float* inp       = (const float*)d_in[0];
    const float* label     = (const float*)d_in[1];
    const float* ea        = (const float*)d_in[2];
    const int*   attribute = (const int*)  d_in[3];
    const float* attr_num  = (const float*)d_in[4];

    const int B = in_sizes[2] / 3;          // ea is [B,3]
    const int D = in_sizes[0] / B;          // inp is [B,D]

    int nblocks = (B + ROWS_PER_BLOCK - 1) / ROWS_PER_BLOCK;   // 2048 for B=32768
    if (nblocks > MAX_PARTIALS) nblocks = MAX_PARTIALS;        // (not hit for this shape)

    loss_rows_kernel<<<nblocks, ROWS_PER_BLOCK * 32>>>(
        inp, label, ea, attribute, attr_num, B, D);

    double inv_count = 1.0 / ((double)B * (double)D);
    final_reduce_kernel<<<1, 1024>>>((float*)d_out, nblocks, inv_count);
}